// round 1
// baseline (speedup 1.0000x reference)
#include <cuda_runtime.h>
#include <math.h>

#define BATCH 4
#define CIN 256
#define COUT 128
#define HH 64
#define WW 64
#define HW 4096
#define BN 64
#define KT 16

// ---------------- scratch (static device globals; no allocs) ----------------
__device__ float g_xc[BATCH * CIN * HW];          // 16 MB
__device__ float g_x1[BATCH * COUT * HW];         // 8 MB
__device__ float g_cat[BATCH * 5 * CIN * HW];     // 80 MB
__device__ float g_proj[BATCH * CIN * HW];        // 16 MB
__device__ float g_xa[BATCH * COUT * HW];         // 8 MB
__device__ float g_O[BATCH * COUT * HW];          // 8 MB
__device__ float g_S[(size_t)BATCH * HW * HW];    // 268 MB (attention scores/probs)
__device__ float g_w3[3 * 9 * CIN * CIN];         // 7 MB transposed conv3x3 weights
__device__ float g_avg[BATCH * CIN];
__device__ float g_mx[BATCH * CIN];
__device__ float g_s[BATCH * CIN];
__device__ float g_bp[BATCH * CIN];

__device__ __forceinline__ float gelu_f(float x) {
    return 0.5f * x * (1.0f + erff(x * 0.70710678118654752440f));
}

// ---------------- per-(b,c) mean & max over HW ----------------
__global__ void k_stats(const float* __restrict__ x) {
    int bc = blockIdx.x;
    const float* p = x + (size_t)bc * HW;
    int t = threadIdx.x;
    float s = 0.f, m = -1e30f;
    for (int i = t; i < HW; i += 256) { float v = p[i]; s += v; m = fmaxf(m, v); }
    __shared__ float ss[256], sm[256];
    ss[t] = s; sm[t] = m; __syncthreads();
    for (int o = 128; o > 0; o >>= 1) {
        if (t < o) { ss[t] += ss[t + o]; sm[t] = fmaxf(sm[t], sm[t + o]); }
        __syncthreads();
    }
    if (t == 0) { g_avg[bc] = ss[0] * (1.f / HW); g_mx[bc] = sm[0]; }
}

// ---------------- channel weighting MLP + global-pool ASPP branch ----------------
__global__ void k_cw(const float* __restrict__ w1, const float* __restrict__ bb1,
                     const float* __restrict__ lg, const float* __restrict__ lb,
                     const float* __restrict__ w2, const float* __restrict__ bb2,
                     const float* __restrict__ apw, const float* __restrict__ apg,
                     const float* __restrict__ apb) {
    int b = blockIdx.x, t = threadIdx.x;
    __shared__ float o[CIN];
    __shared__ float h[COUT];
    __shared__ float red[256];
    __shared__ float gp[CIN];
    float avg = g_avg[b * CIN + t], mx = g_mx[b * CIN + t];
    o[t] = fabsf(avg - mx) * avg;
    __syncthreads();
    float hv = 0.f;
    if (t < COUT) {
        hv = bb1[t];
        const float* wr = w1 + t * CIN;
        for (int i = 0; i < CIN; i++) hv = fmaf(o[i], wr[i], hv);
    }
    red[t] = (t < COUT) ? hv : 0.f; __syncthreads();
    for (int s = 128; s > 0; s >>= 1) { if (t < s) red[t] += red[t + s]; __syncthreads(); }
    float mu = red[0] * (1.f / COUT); __syncthreads();
    float dv = (t < COUT) ? (hv - mu) : 0.f;
    red[t] = dv * dv; __syncthreads();
    for (int s = 128; s > 0; s >>= 1) { if (t < s) red[t] += red[t + s]; __syncthreads(); }
    float var = red[0] * (1.f / COUT); __syncthreads();
    if (t < COUT) h[t] = lg[t] * ((hv - mu) * rsqrtf(var + 1e-5f)) + lb[t];
    __syncthreads();
    float sv = bb2[t];
    const float* wr2 = w2 + t * COUT;
    for (int j = 0; j < COUT; j++) sv = fmaf(h[j], wr2[j], sv);
    float sig = 1.f / (1.f + expf(-sv));
    g_s[b * CIN + t] = sig;
    gp[t] = (1.f + sig) * avg;     // mean of xc = (1+s) * mean(x)
    __syncthreads();
    float v = 0.f;
    const float* ar = apw + t * CIN;
    for (int i = 0; i < CIN; i++) v = fmaf(ar[i], gp[i], v);
    red[t] = v; __syncthreads();
    for (int s = 128; s > 0; s >>= 1) { if (t < s) red[t] += red[t + s]; __syncthreads(); }
    float mu2 = red[0] * (1.f / CIN); __syncthreads();
    float d2 = v - mu2; red[t] = d2 * d2; __syncthreads();
    for (int s = 128; s > 0; s >>= 1) { if (t < s) red[t] += red[t + s]; __syncthreads(); }
    float var2 = red[0] * (1.f / CIN); __syncthreads();
    float z = apg[t] * ((v - mu2) * rsqrtf(var2 + 1e-6f)) + apb[t];
    g_bp[b * CIN + t] = gelu_f(z);
}

// ---------------- xc = x * (1 + s) ----------------
__global__ void k_xc(const float* __restrict__ x) {
    int idx = blockIdx.x * 256 + threadIdx.x;
    const int n4 = BATCH * CIN * HW / 4;
    if (idx < n4) {
        int bc = idx / (HW / 4);
        float sc = 1.f + g_s[bc];
        float4 v = reinterpret_cast<const float4*>(x)[idx];
        v.x *= sc; v.y *= sc; v.z *= sc; v.w *= sc;
        reinterpret_cast<float4*>(g_xc)[idx] = v;
    }
}

// ---------------- broadcast bp into cat channels [1024,1280) ----------------
__global__ void k_bp() {
    int bc = blockIdx.x;
    int b = bc >> 8, c = bc & 255;
    float v = g_bp[bc];
    float4* dst = reinterpret_cast<float4*>(g_cat + ((size_t)b * 5 * CIN + 4 * CIN + c) * HW);
    float4 v4 = make_float4(v, v, v, v);
    for (int i = threadIdx.x; i < HW / 4; i += 256) dst[i] = v4;
}

// ---------------- transpose conv3x3 weights to [tap][m][c] ----------------
__global__ void k_transw(const float* __restrict__ w1, const float* __restrict__ w2,
                         const float* __restrict__ w3) {
    int e = blockIdx.x * 256 + threadIdx.x;   // 3 * 256 * 256
    if (e >= 3 * 65536) return;
    const float* srcs[3] = { w1, w2, w3 };
    int conv = e >> 16, mc = e & 65535, m = mc >> 8, c = mc & 255;
    const float* src = srcs[conv] + (size_t)m * 2304 + (size_t)c * 9;
    float* dst = g_w3 + (size_t)conv * 9 * 65536 + (size_t)m * 256 + c;
#pragma unroll
    for (int tap = 0; tap < 9; tap++) dst[(size_t)tap * 65536] = src[tap];
}

// ---------------- generic GEMM: Out[b,m,n] = sum_k W[m,k] * In[b,k,n] ----------------
// MODE 0: + bias[m]
// MODE 1: channels-first LayerNorm over m (eps 1e-6) + exact GELU  (requires BM == full M == 256)
// MODE 2: + Add[b,m,n]
// CONV3: implicit dilated 3x3 over taps; W is g_w3 layout [tap][m][c] (Kc=256), In is xc.
template <int BM, int MODE, bool CONV3>
__global__ void __launch_bounds__(256) k_gemm(
    const float* __restrict__ Wg, size_t wb_stride,
    const float* __restrict__ In, size_t in_bstride,
    const float* __restrict__ P1, const float* __restrict__ P2,
    const float* __restrict__ Addp, size_t add_bstride,
    float* __restrict__ Out, size_t out_bstride,
    int Kc, int dil) {
    constexpr int TM = BM / 32;
    const int b = blockIdx.y;
    const int y = blockIdx.x;          // spatial row; n0 = y*64
    const int n0 = y * BN;
    const int t = threadIdx.x;
    const int ty = t >> 3, tx = t & 7;

    __shared__ __align__(16) float As[KT][BM];
    __shared__ __align__(16) float Bs[KT][BN];
    __shared__ float red[(MODE == 1) ? 32 : 1][BN];
    __shared__ float cmean[BN], crstd[BN];

    float acc[TM][8];
#pragma unroll
    for (int i = 0; i < TM; i++)
#pragma unroll
        for (int j = 0; j < 8; j++) acc[i][j] = 0.f;

    const float* Wb = Wg + (size_t)b * wb_stride;
    const float* Inb = In + (size_t)b * in_bstride;

    const int ntaps = CONV3 ? 9 : 1;
    for (int tap = 0; tap < ntaps; ++tap) {
        int yy = y, dx = 0; bool rowok = true;
        if (CONV3) {
            int dy = (tap / 3 - 1) * dil;
            dx = (tap % 3 - 1) * dil;
            yy = y + dy;
            rowok = ((unsigned)yy < (unsigned)HH);
        }
        for (int k0 = 0; k0 < Kc; k0 += KT) {
            // ---- A tile -> As[k][m]
            if (BM == 256) {
                int rowidx = CONV3 ? (tap * BM + t) : t;
                const float* wrow = Wb + (size_t)rowidx * Kc + k0;
#pragma unroll
                for (int q = 0; q < 4; q++) {
                    float4 v = *reinterpret_cast<const float4*>(wrow + q * 4);
                    As[q * 4 + 0][t] = v.x; As[q * 4 + 1][t] = v.y;
                    As[q * 4 + 2][t] = v.z; As[q * 4 + 3][t] = v.w;
                }
            } else {  // BM == 128
                int m = t >> 1, ko = (t & 1) * 8;
                const float* wrow = Wb + (size_t)m * Kc + k0 + ko;
#pragma unroll
                for (int q = 0; q < 2; q++) {
                    float4 v = *reinterpret_cast<const float4*>(wrow + q * 4);
                    As[ko + q * 4 + 0][m] = v.x; As[ko + q * 4 + 1][m] = v.y;
                    As[ko + q * 4 + 2][m] = v.z; As[ko + q * 4 + 3][m] = v.w;
                }
            }
            // ---- B tile -> Bs[k][n]
            {
                int k = t >> 4, nb = (t & 15) * 4;
                if (!CONV3) {
                    float4 v = *reinterpret_cast<const float4*>(
                        Inb + (size_t)(k0 + k) * HW + n0 + nb);
                    *reinterpret_cast<float4*>(&Bs[k][nb]) = v;
                } else {
                    const float* src = Inb + (size_t)(k0 + k) * HW + yy * WW;
#pragma unroll
                    for (int q = 0; q < 4; q++) {
                        int xx = nb + q + dx;
                        float v = 0.f;
                        if (rowok && xx >= 0 && xx < WW) v = src[xx];
                        Bs[k][nb + q] = v;
                    }
                }
            }
            __syncthreads();
#pragma unroll
            for (int k = 0; k < KT; k++) {
                float a[TM], bb[8];
#pragma unroll
                for (int i = 0; i < TM; i += 4) {
                    float4 v = *reinterpret_cast<const float4*>(&As[k][ty * TM + i]);
                    a[i] = v.x; a[i + 1] = v.y; a[i + 2] = v.z; a[i + 3] = v.w;
                }
#pragma unroll
                for (int j = 0; j < 8; j += 4) {
                    float4 v = *reinterpret_cast<const float4*>(&Bs[k][tx * 8 + j]);
                    bb[j] = v.x; bb[j + 1] = v.y; bb[j + 2] = v.z; bb[j + 3] = v.w;
                }
#pragma unroll
                for (int i = 0; i < TM; i++)
#pragma unroll
                    for (int j = 0; j < 8; j++) acc[i][j] = fmaf(a[i], bb[j], acc[i][j]);
            }
            __syncthreads();
        }
    }

    float* Ob = Out + (size_t)b * out_bstride;
    if (MODE == 1) {
        float ps[8];
#pragma unroll
        for (int j = 0; j < 8; j++) {
            float s = 0.f;
#pragma unroll
            for (int i = 0; i < TM; i++) s += acc[i][j];
            red[ty][tx * 8 + j] = s;
        }
        __syncthreads();
        if (t < BN) {
            float s = 0.f;
#pragma unroll
            for (int r = 0; r < 32; r++) s += red[r][t];
            cmean[t] = s * (1.f / BM);
        }
        __syncthreads();
#pragma unroll
        for (int j = 0; j < 8; j++) {
            float s = 0.f;
#pragma unroll
            for (int i = 0; i < TM; i++) { float d = acc[i][j]; s += d * d; }
            red[ty][tx * 8 + j] = s;
        }
        __syncthreads();
        if (t < BN) {
            float s = 0.f;
#pragma unroll
            for (int r = 0; r < 32; r++) s += red[r][t];
            float m = cmean[t];
            float var = s * (1.f / BM) - m * m;
            crstd[t] = rsqrtf(var + 1e-6f);
        }
        __syncthreads();
#pragma unroll
        for (int i = 0; i < TM; i++) {
            int m = ty * TM + i;
            float gmm = P1[m], bet = P2[m];
            float o8[8];
#pragma unroll
            for (int j = 0; j < 8; j++) {
                int n = tx * 8 + j;
                float v = (acc[i][j] - cmean[n]) * crstd[n] * gmm + bet;
                o8[j] = gelu_f(v);
            }
            float* dst = Ob + (size_t)m * HW + n0 + tx * 8;
            *reinterpret_cast<float4*>(dst) = make_float4(o8[0], o8[1], o8[2], o8[3]);
            *reinterpret_cast<float4*>(dst + 4) = make_float4(o8[4], o8[5], o8[6], o8[7]);
        }
    } else {
#pragma unroll
        for (int i = 0; i < TM; i++) {
            int m = ty * TM + i;
            float bias = (MODE == 0) ? P1[m] : 0.f;
            const float* addrow = (MODE == 2)
                ? (Addp + (size_t)b * add_bstride + (size_t)m * HW + n0 + tx * 8)
                : nullptr;
            float o8[8];
#pragma unroll
            for (int j = 0; j < 8; j++) {
                float v = acc[i][j] + bias;
                if (MODE == 2) v += addrow[j];
                o8[j] = v;
            }
            float* dst = Ob + (size_t)m * HW + n0 + tx * 8;
            *reinterpret_cast<float4*>(dst) = make_float4(o8[0], o8[1], o8[2], o8[3]);
            *reinterpret_cast<float4*>(dst + 4) = make_float4(o8[4], o8[5], o8[6], o8[7]);
        }
    }
}

// ---------------- S[b,q,p] = (1/64) sum_c xa[b,c,q] * x1[b,c,p] ----------------
__global__ void __launch_bounds__(256) k_sgemm() {
    const int b = blockIdx.z;
    const int m0 = blockIdx.y * 128;
    const int n0 = blockIdx.x * 64;
    const int t = threadIdx.x, ty = t >> 3, tx = t & 7;
    const float* Q = g_xa + (size_t)b * COUT * HW;
    const float* P = g_x1 + (size_t)b * COUT * HW;
    float* S = g_S + (size_t)b * HW * HW;
    __shared__ __align__(16) float As[KT][128];
    __shared__ __align__(16) float Bs[KT][64];
    float acc[4][8];
#pragma unroll
    for (int i = 0; i < 4; i++)
#pragma unroll
        for (int j = 0; j < 8; j++) acc[i][j] = 0.f;

    for (int k0 = 0; k0 < COUT; k0 += KT) {
        int k = t >> 4;
        {
            int mm = (t & 15) * 8;
            const float* src = Q + (size_t)(k0 + k) * HW + m0 + mm;
            *reinterpret_cast<float4*>(&As[k][mm]) = *reinterpret_cast<const float4*>(src);
            *reinterpret_cast<float4*>(&As[k][mm + 4]) = *reinterpret_cast<const float4*>(src + 4);
        }
        {
            int nb = (t & 15) * 4;
            *reinterpret_cast<float4*>(&Bs[k][nb]) =
                *reinterpret_cast<const float4*>(P + (size_t)(k0 + k) * HW + n0 + nb);
        }
        __syncthreads();
#pragma unroll
        for (int kk = 0; kk < KT; kk++) {
            float a[4], bb[8];
            float4 va = *reinterpret_cast<const float4*>(&As[kk][ty * 4]);
            a[0] = va.x; a[1] = va.y; a[2] = va.z; a[3] = va.w;
#pragma unroll
            for (int j = 0; j < 8; j += 4) {
                float4 v = *reinterpret_cast<const float4*>(&Bs[kk][tx * 8 + j]);
                bb[j] = v.x; bb[j + 1] = v.y; bb[j + 2] = v.z; bb[j + 3] = v.w;
            }
#pragma unroll
            for (int i = 0; i < 4; i++)
#pragma unroll
                for (int j = 0; j < 8; j++) acc[i][j] = fmaf(a[i], bb[j], acc[i][j]);
        }
        __syncthreads();
    }
    const float sc = 1.f / 64.f;
#pragma unroll
    for (int i = 0; i < 4; i++) {
        int m = ty * 4 + i;
        float* dst = S + (size_t)(m0 + m) * HW + n0 + tx * 8;
        *reinterpret_cast<float4*>(dst) =
            make_float4(acc[i][0] * sc, acc[i][1] * sc, acc[i][2] * sc, acc[i][3] * sc);
        *reinterpret_cast<float4*>(dst + 4) =
            make_float4(acc[i][4] * sc, acc[i][5] * sc, acc[i][6] * sc, acc[i][7] * sc);
    }
}

// ---------------- row softmax over p (in place on g_S) ----------------
__global__ void __launch_bounds__(256) k_softmax() {
    const size_t row = blockIdx.x;
    float* r = g_S + row * (size_t)HW;
    __shared__ float buf[HW];
    __shared__ float red[256];
    int t = threadIdx.x;
    float m = -1e30f;
    for (int i = t; i < HW; i += 256) { float v = r[i]; buf[i] = v; m = fmaxf(m, v); }
    red[t] = m; __syncthreads();
    for (int s = 128; s > 0; s >>= 1) { if (t < s) red[t] = fmaxf(red[t], red[t + s]); __syncthreads(); }
    float mx = red[0]; __syncthreads();
    float s = 0.f;
    for (int i = t; i < HW; i += 256) { float e = expf(buf[i] - mx); buf[i] = e; s += e; }
    red[t] = s; __syncthreads();
    for (int o = 128; o > 0; o >>= 1) { if (t < o) red[t] += red[t + o]; __syncthreads(); }
    float inv = 1.f / red[0];
    for (int i = t; i < HW; i += 256) r[i] = buf[i] * inv;
}

// ---------------- host launch ----------------
extern "C" void kernel_launch(void* const* d_in, const int* in_sizes, int n_in,
                              void* d_out, int out_size) {
    (void)in_sizes; (void)n_in; (void)out_size;
    const float* x       = (const float*)d_in[0];
    const float* conv1_w = (const float*)d_in[1];
    const float* conv1_b = (const float*)d_in[2];
    const float* conv2_w = (const float*)d_in[3];
    const float* conv2_b = (const float*)d_in[4];
    const float* cw_w1   = (const float*)d_in[5];
    const float* cw_b1   = (const float*)d_in[6];
    const float* cw_ln_g = (const float*)d_in[7];
    const float* cw_ln_b = (const float*)d_in[8];
    const float* cw_w2   = (const float*)d_in[9];
    const float* cw_b2   = (const float*)d_in[10];
    const float* aspp0_w = (const float*)d_in[11];
    const float* aspp0_g = (const float*)d_in[12];
    const float* aspp0_b = (const float*)d_in[13];
    const float* aspp1_w = (const float*)d_in[14];
    const float* aspp1_g = (const float*)d_in[15];
    const float* aspp1_b = (const float*)d_in[16];
    const float* aspp2_w = (const float*)d_in[17];
    const float* aspp2_g = (const float*)d_in[18];
    const float* aspp2_b = (const float*)d_in[19];
    const float* aspp3_w = (const float*)d_in[20];
    const float* aspp3_g = (const float*)d_in[21];
    const float* aspp3_b = (const float*)d_in[22];
    const float* asppp_w = (const float*)d_in[23];
    const float* asppp_g = (const float*)d_in[24];
    const float* asppp_b = (const float*)d_in[25];
    const float* proj_w  = (const float*)d_in[26];
    const float* proj_g  = (const float*)d_in[27];
    const float* proj_b  = (const float*)d_in[28];

    void* pv;
    float *p_xc, *p_x1, *p_cat, *p_proj, *p_xa, *p_O, *p_S, *p_w3;
    cudaGetSymbolAddress(&pv, g_xc);   p_xc   = (float*)pv;
    cudaGetSymbolAddress(&pv, g_x1);   p_x1   = (float*)pv;
    cudaGetSymbolAddress(&pv, g_cat);  p_cat  = (float*)pv;
    cudaGetSymbolAddress(&pv, g_proj); p_proj = (float*)pv;
    cudaGetSymbolAddress(&pv, g_xa);   p_xa   = (float*)pv;
    cudaGetSymbolAddress(&pv, g_O);    p_O    = (float*)pv;
    cudaGetSymbolAddress(&pv, g_S);    p_S    = (float*)pv;
    cudaGetSymbolAddress(&pv, g_w3);   p_w3   = (float*)pv;

    dim3 g64(HW / BN, BATCH);

    k_stats<<<BATCH * CIN, 256>>>(x);
    k_cw<<<BATCH, 256>>>(cw_w1, cw_b1, cw_ln_g, cw_ln_b, cw_w2, cw_b2,
                         asppp_w, asppp_g, asppp_b);
    k_xc<<<(BATCH * CIN * HW / 4 + 255) / 256, 256>>>(x);
    k_transw<<<768, 256>>>(aspp1_w, aspp2_w, aspp3_w);
    k_bp<<<BATCH * CIN, 256>>>();

    // x1 = conv1(x) + b
    k_gemm<128, 0, false><<<g64, 256>>>(conv1_w, 0, x, (size_t)CIN * HW,
                                        conv1_b, nullptr, nullptr, 0,
                                        p_x1, (size_t)COUT * HW, CIN, 0);
    // ASPP branches into cat
    k_gemm<256, 1, false><<<g64, 256>>>(aspp0_w, 0, p_xc, (size_t)CIN * HW,
                                        aspp0_g, aspp0_b, nullptr, 0,
                                        p_cat, (size_t)5 * CIN * HW, CIN, 0);
    k_gemm<256, 1, true><<<g64, 256>>>(p_w3 + 0 * 9 * CIN * CIN, 0, p_xc, (size_t)CIN * HW,
                                       aspp1_g, aspp1_b, nullptr, 0,
                                       p_cat + 1 * CIN * HW, (size_t)5 * CIN * HW, CIN, 3);
    k_gemm<256, 1, true><<<g64, 256>>>(p_w3 + 1 * 9 * CIN * CIN, 0, p_xc, (size_t)CIN * HW,
                                       aspp2_g, aspp2_b, nullptr, 0,
                                       p_cat + 2 * CIN * HW, (size_t)5 * CIN * HW, CIN, 6);
    k_gemm<256, 1, true><<<g64, 256>>>(p_w3 + 2 * 9 * CIN * CIN, 0, p_xc, (size_t)CIN * HW,
                                       aspp3_g, aspp3_b, nullptr, 0,
                                       p_cat + 3 * CIN * HW, (size_t)5 * CIN * HW, CIN, 9);
    // proj = gelu(LN(conv1x1(cat)))
    k_gemm<256, 1, false><<<g64, 256>>>(proj_w, 0, p_cat, (size_t)5 * CIN * HW,
                                        proj_g, proj_b, nullptr, 0,
                                        p_proj, (size_t)CIN * HW, 5 * CIN, 0);
    // xa = conv1(proj) + b
    k_gemm<128, 0, false><<<g64, 256>>>(conv1_w, 0, p_proj, (size_t)CIN * HW,
                                        conv1_b, nullptr, nullptr, 0,
                                        p_xa, (size_t)COUT * HW, CIN, 0);
    // attention
    k_sgemm<<<dim3(HW / 64, HW / 128, BATCH), 256>>>();
    k_softmax<<<BATCH * HW, 256>>>();
    // L = x1 @ A  (+ xa)
    k_gemm<128, 2, false><<<g64, 256>>>(p_x1, (size_t)COUT * HW, p_S, (size_t)HW * HW,
                                        nullptr, nullptr, p_xa, (size_t)COUT * HW,
                                        p_O, (size_t)COUT * HW, HW, 0);
    // out = conv2(O) + b
    k_gemm<256, 0, false><<<g64, 256>>>(conv2_w, 0, p_O, (size_t)COUT * HW,
                                        conv2_b, nullptr, nullptr, 0,
                                        (float*)d_out, (size_t)CIN * HW, COUT, 0);
}